// round 3
// baseline (speedup 1.0000x reference)
#include <cuda_runtime.h>
#include <math.h>

#define LNUM 102
#define LPAD 104
#define NPAIR (LPAD / 2)          // 52 packed f32x2 pairs per row
#define NT   128
#define MAXB 1024
#define G    2                    // batches per block

__device__ int g_perm[MAXB];

typedef unsigned long long ull;

// ---------- packed f32x2 helpers ----------
__device__ __forceinline__ void fma2(ull& d, ull a, ull b) {
    asm("fma.rn.f32x2 %0, %1, %2, %0;" : "+l"(d) : "l"(a), "l"(b));
}
__device__ __forceinline__ ull add2(ull a, ull b) {
    ull r; asm("add.rn.f32x2 %0, %1, %2;" : "=l"(r) : "l"(a), "l"(b)); return r;
}
__device__ __forceinline__ float2 unpack2(ull u) {
    float2 f; asm("mov.b64 {%0, %1}, %2;" : "=f"(f.x), "=f"(f.y) : "l"(u)); return f;
}
__device__ __forceinline__ ull pack2(float x, float y) {
    ull u; asm("mov.b64 %0, {%1, %2};" : "=l"(u) : "f"(x), "f"(y)); return u;
}

// ---------- LPT pre-sort: order batches by descending length ----------
__global__ void sort_kernel(const int* __restrict__ lens, int B) {
    __shared__ int keys[MAXB];
    const int tid = threadIdx.x;
    for (int i = tid; i < MAXB; i += blockDim.x)
        keys[i] = (i < B) ? ((lens[i] << 10) | (MAXB - 1 - i)) : -1;
    __syncthreads();
    for (int k = 2; k <= MAXB; k <<= 1) {
        for (int j = k >> 1; j > 0; j >>= 1) {
            for (int i = tid; i < MAXB; i += blockDim.x) {
                int ixj = i ^ j;
                if (ixj > i) {
                    int a = keys[i], c = keys[ixj];
                    bool seg = ((i & k) == 0);   // descending
                    if (seg ? (a < c) : (a > c)) { keys[i] = c; keys[ixj] = a; }
                }
            }
            __syncthreads();
        }
    }
    for (int i = tid; i < B; i += blockDim.x)
        g_perm[i] = (MAXB - 1) - (keys[i] & (MAXB - 1));
}

// ---------- main CRF forward: 2 batches/block, linear domain, lazy renorm ----------
__global__ __launch_bounds__(NT, 3)
void crf_fwd_kernel(const float* __restrict__ logits,
                    const float* __restrict__ trans,
                    const int*   __restrict__ lens,
                    float* __restrict__ out,
                    int T, int B)
{
    const int j    = threadIdx.x;
    const int lane = j & 31;
    const int warp = j >> 5;

    const int i0 = 2 * blockIdx.x, i1 = 2 * blockIdx.x + 1;
    const int ba = g_perm[i0];
    const int bb = (i1 < B) ? g_perm[i1] : ba;

    __shared__ __align__(16) float q_sh[2][G][LPAD];
    __shared__ float redA[4], redB[4];

    // E[j,k] = exp(trans[j,k]) as 52 packed pairs (pads = 0)
    ull E2[NPAIR];
    #pragma unroll
    for (int m = 0; m < NPAIR; ++m) {
        float a = 0.f, c = 0.f;
        if (j < LNUM) {
            const float* tr = trans + (size_t)j * LNUM;
            int k = 2 * m;
            if (k + 0 < LNUM) a = __expf(tr[k + 0]);
            if (k + 1 < LNUM) c = __expf(tr[k + 1]);
        }
        E2[m] = pack2(a, c);
    }

    // init q = exp(alpha0): 1 at start label
    if (j < LPAD) {
        float qi = (j == LNUM - 2) ? 1.f : 0.f;
        q_sh[0][0][j] = qi; q_sh[0][1][j] = qi;
        q_sh[1][0][j] = 0.f; q_sh[1][1][j] = 0.f;
    }
    float qa = (j == LNUM - 2) ? 1.f : 0.f;
    float qb = qa;

    int len_a = lens[ba]; if (len_a > T) len_a = T;
    int len_b = lens[bb]; if (len_b > T) len_b = T;
    const int maxlen = (len_a > len_b) ? len_a : len_b;

    const float* lga = logits + (size_t)ba * T * LNUM;
    const float* lgb = logits + (size_t)bb * T * LNUM;

    float Ca = 0.f, Cb = 0.f;
    int cur = 0;

    float lgva = (maxlen > 0 && j < LNUM) ? lga[j] : 0.f;
    float lgvb = (maxlen > 0 && j < LNUM) ? lgb[j] : 0.f;

    __syncthreads();

    for (int t = 0; t < maxlen; ++t) {
        // apply pending renorm scale (from max taken at t-1 ≡ 3 mod 4)
        float sa = 1.f, sb = 1.f;
        if ((t & 3) == 0 && t > 0) {
            float Ma = fmaxf(fmaxf(redA[0], redA[1]), fmaxf(redA[2], redA[3]));
            float Mb = fmaxf(fmaxf(redB[0], redB[1]), fmaxf(redB[2], redB[3]));
            Ma = fmaxf(Ma, 1e-35f); Mb = fmaxf(Mb, 1e-35f);
            sa = __fdividef(1.f, Ma); Ca += __logf(Ma);
            sb = __fdividef(1.f, Mb); Cb += __logf(Mb);
        }

        const float ela = __expf(lgva);
        const float elb = __expf(lgvb);

        // prefetch next step's logits (overlaps matvec + barrier)
        const int tn = (t + 1 < T) ? (t + 1) : t;
        const float lgva_n = (j < LNUM) ? lga[(size_t)tn * LNUM + j] : 0.f;
        const float lgvb_n = (j < LNUM) ? lgb[(size_t)tn * LNUM + j] : 0.f;

        // dual matvec: y[j] = sum_k E[j,k] * q[k], both batches interleaved
        ull aa0 = 0ull, aa1 = 0ull, ab0 = 0ull, ab1 = 0ull;
        const ulonglong2* pa = reinterpret_cast<const ulonglong2*>(q_sh[cur][0]);
        const ulonglong2* pb = reinterpret_cast<const ulonglong2*>(q_sh[cur][1]);
        #pragma unroll
        for (int m = 0; m < NPAIR / 2; ++m) {
            ulonglong2 va = pa[m];
            ulonglong2 vb = pb[m];
            fma2(aa0, E2[2 * m],     va.x);
            fma2(ab0, E2[2 * m],     vb.x);
            fma2(aa1, E2[2 * m + 1], va.y);
            fma2(ab1, E2[2 * m + 1], vb.y);
        }
        float2 fa = unpack2(add2(aa0, aa1));
        float2 fb = unpack2(add2(ab0, ab1));
        const float ya = fa.x + fa.y;
        const float yb = fb.x + fb.y;

        // q' = s * exp(logit) * (E q); frozen batches keep q (scaled)
        qa = sa * ((t < len_a) ? ela * ya : qa);
        qb = sb * ((t < len_b) ? elb * yb : qb);

        // renorm measurement every 4th step (no extra barrier: reuses step barrier)
        if ((t & 3) == 3) {
            float ma = qa, mb = qb;
            #pragma unroll
            for (int o = 16; o; o >>= 1) {
                ma = fmaxf(ma, __shfl_xor_sync(0xffffffffu, ma, o));
                mb = fmaxf(mb, __shfl_xor_sync(0xffffffffu, mb, o));
            }
            if (lane == 0) { redA[warp] = ma; redB[warp] = mb; }
        }

        if (j < LPAD) {
            q_sh[cur ^ 1][0][j] = qa;
            q_sh[cur ^ 1][1][j] = qb;
        }
        lgva = lgva_n; lgvb = lgvb_n;
        __syncthreads();
        cur ^= 1;
    }

    // out = C + log( sum_j q[j] * exp(trans[stop, j]) )
    // (any un-applied renorm cancels exactly: C not bumped, q not scaled)
    float es = (j < LNUM) ? __expf(trans[(size_t)(LNUM - 1) * LNUM + j]) : 0.f;
    float va = qa * es, vb = qb * es;
    #pragma unroll
    for (int o = 16; o; o >>= 1) {
        va += __shfl_xor_sync(0xffffffffu, va, o);
        vb += __shfl_xor_sync(0xffffffffu, vb, o);
    }
    if (lane == 0) { redA[warp] = va; redB[warp] = vb; }
    __syncthreads();
    if (j == 0) {
        float s_a = (redA[0] + redA[1]) + (redA[2] + redA[3]);
        out[ba] = Ca + logf(s_a);
    }
    if (j == 1 && bb != ba) {
        float s_b = (redB[0] + redB[1]) + (redB[2] + redB[3]);
        out[bb] = Cb + logf(s_b);
    }
}

extern "C" void kernel_launch(void* const* d_in, const int* in_sizes, int n_in,
                              void* d_out, int out_size)
{
    const float* logits = (const float*)d_in[0];   // [B, T, L] f32
    const float* trans  = (const float*)d_in[1];   // [L, L]    f32
    const int*   lens   = (const int*)d_in[2];     // [B]       i32
    float*       out    = (float*)d_out;           // [B]       f32

    const int B = in_sizes[2];
    const int T = in_sizes[0] / (B * LNUM);
    const int nblk = (B + G - 1) / G;

    sort_kernel<<<1, MAXB>>>(lens, B);
    crf_fwd_kernel<<<nblk, NT>>>(logits, trans, lens, out, T, B);
}

// round 4
// speedup vs baseline: 1.3746x; 1.3746x over previous
#include <cuda_runtime.h>
#include <math.h>

#define LNUM 102
#define LPAD 104
#define NPAIR 52                  // packed f32x2 pairs per row
#define NT   128
#define MAXB 1024

__device__ int g_perm[MAXB];
typedef unsigned long long ull;

// ---------- packed f32x2 helpers ----------
__device__ __forceinline__ void fma2(ull& d, ull a, ull b) {
    asm("fma.rn.f32x2 %0, %1, %2, %0;" : "+l"(d) : "l"(a), "l"(b));
}
__device__ __forceinline__ ull add2(ull a, ull b) {
    ull r; asm("add.rn.f32x2 %0, %1, %2;" : "=l"(r) : "l"(a), "l"(b)); return r;
}
__device__ __forceinline__ float2 unpack2(ull u) {
    float2 f; asm("mov.b64 {%0, %1}, %2;" : "=f"(f.x), "=f"(f.y) : "l"(u)); return f;
}
__device__ __forceinline__ ull pack2(float x, float y) {
    ull u; asm("mov.b64 %0, {%1, %2};" : "=l"(u) : "f"(x), "f"(y)); return u;
}

// ---------- LPT pre-sort: order batches by descending length ----------
__global__ void sort_kernel(const int* __restrict__ lens, int B) {
    __shared__ int keys[MAXB];
    const int tid = threadIdx.x;
    for (int i = tid; i < MAXB; i += blockDim.x)
        keys[i] = (i < B) ? ((lens[i] << 10) | (MAXB - 1 - i)) : -1;
    __syncthreads();
    for (int k = 2; k <= MAXB; k <<= 1) {
        for (int j = k >> 1; j > 0; j >>= 1) {
            for (int i = tid; i < MAXB; i += blockDim.x) {
                int ixj = i ^ j;
                if (ixj > i) {
                    int a = keys[i], c = keys[ixj];
                    bool seg = ((i & k) == 0);   // descending
                    if (seg ? (a < c) : (a > c)) { keys[i] = c; keys[ixj] = a; }
                }
            }
            __syncthreads();
        }
    }
    for (int i = tid; i < B; i += blockDim.x)
        g_perm[i] = (MAXB - 1) - (keys[i] & (MAXB - 1));
}

// ---------- CRF forward: linear domain, 4-step chunks, redundant renorm ----------
__global__ __launch_bounds__(NT, 3)
void crf_fwd_kernel(const float* __restrict__ logits,
                    const float* __restrict__ trans,
                    const int*   __restrict__ lens,
                    float* __restrict__ out,
                    int T)
{
    const int b    = g_perm[blockIdx.x];
    const int j    = threadIdx.x;
    const int lane = j & 31;
    const int warp = j >> 5;

    __shared__ __align__(16) float q_sh[2][LPAD];
    __shared__ float red[4];

    // E[j,k] = exp(trans[j,k]) as 52 packed f32x2 pairs (pads = 0)
    ull E2[NPAIR];
    #pragma unroll
    for (int m = 0; m < NPAIR; ++m) {
        float a = 0.f, c = 0.f;
        if (j < LNUM) {
            const float* tr = trans + (size_t)j * LNUM;
            int k = 2 * m;
            if (k + 0 < LNUM) a = __expf(tr[k + 0]);
            if (k + 1 < LNUM) c = __expf(tr[k + 1]);
        }
        E2[m] = pack2(a, c);
    }

    // init q = exp(alpha0): 1 at start label, 0 elsewhere
    float q = (j == LNUM - 2) ? 1.f : 0.f;
    if (j < LPAD) { q_sh[0][j] = q; q_sh[1][j] = 0.f; }

    int len = lens[b];
    if (len > T) len = T;
    const float* lg = logits + (size_t)b * T * LNUM;

    float C = 0.f;

    // preload logits for steps 0..3 (depth-4 pipeline)
    float lgq[4];
    #pragma unroll
    for (int u = 0; u < 4; ++u)
        lgq[u] = (u < len && j < LNUM) ? lg[(size_t)u * LNUM + j] : 0.f;

    __syncthreads();

    for (int tc = 0; tc < len; tc += 4) {
        // prefetch next chunk's logits: 4 independent LDGs (MLP=4) covering DRAM lat
        float lgn[4];
        #pragma unroll
        for (int u = 0; u < 4; ++u) {
            int tl = tc + 4 + u;
            lgn[u] = (tl < len && j < LNUM) ? lg[(size_t)tl * LNUM + j] : 0.f;
        }

        #pragma unroll
        for (int u = 0; u < 4; ++u) {
            const int t = tc + u;
            if (t >= len) break;                       // uniform across block

            const float el = __expf(lgq[u]);

            // y[j] = sum_k E[j,k] * q[k]; on u==0 also fold a redundant
            // block-max of q (every thread sees full q -> identical result,
            // FMNMX on alu pipe overlaps FMA2 on fma pipe)
            ull a0 = 0ull, a1 = 0ull, a2 = 0ull, a3 = 0ull;
            float m0 = 0.f, m1 = 0.f;
            const ulonglong2* ps =
                reinterpret_cast<const ulonglong2*>(q_sh[u & 1]);
            #pragma unroll
            for (int m = 0; m < NPAIR / 2; ++m) {      // 26 LDS.128
                ulonglong2 v = ps[m];
                fma2(a0, E2[2 * m],     v.x);
                fma2(a1, E2[2 * m + 1], v.y);
                if (u == 0) {
                    float2 fx = unpack2(v.x), fy = unpack2(v.y);
                    m0 = fmaxf(m0, fmaxf(fx.x, fx.y));
                    m1 = fmaxf(m1, fmaxf(fy.x, fy.y));
                }
                ++m;
                if (m < NPAIR / 2) {
                    ulonglong2 w = ps[m];
                    fma2(a2, E2[2 * m],     w.x);
                    fma2(a3, E2[2 * m + 1], w.y);
                    if (u == 0) {
                        float2 gx = unpack2(w.x), gy = unpack2(w.y);
                        m0 = fmaxf(m0, fmaxf(gx.x, gx.y));
                        m1 = fmaxf(m1, fmaxf(gy.x, gy.y));
                    }
                }
            }
            ull s = add2(add2(a0, a1), add2(a2, a3));
            float2 fs = unpack2(s);
            float y = fs.x + fs.y;

            if (u == 0 && t > 0) {
                // uniform renormalization, no communication
                const float M  = fmaxf(fmaxf(m0, m1), 1e-30f);
                const float rM = __fdividef(1.f, M);
                C += __logf(M);
                y *= rM;
            }

            q = el * y;                                // pads: E2=0 -> y=0 -> q=0
            if (j < LPAD) q_sh[(u + 1) & 1][j] = q;
            __syncthreads();
        }

        #pragma unroll
        for (int u = 0; u < 4; ++u) lgq[u] = lgn[u];
    }

    // out[b] = C + log( sum_j q[j] * exp(trans[stop, j]) )
    float v = (j < LNUM)
        ? q * __expf(trans[(size_t)(LNUM - 1) * LNUM + j]) : 0.f;
    #pragma unroll
    for (int o = 16; o; o >>= 1)
        v += __shfl_xor_sync(0xffffffffu, v, o);
    if (lane == 0) red[warp] = v;
    __syncthreads();
    if (j == 0) {
        float sum = (red[0] + red[1]) + (red[2] + red[3]);
        out[b] = C + logf(sum);
    }
}

extern "C" void kernel_launch(void* const* d_in, const int* in_sizes, int n_in,
                              void* d_out, int out_size)
{
    const float* logits = (const float*)d_in[0];   // [B, T, L] f32
    const float* trans  = (const float*)d_in[1];   // [L, L]    f32
    const int*   lens   = (const int*)d_in[2];     // [B]       i32
    float*       out    = (float*)d_out;           // [B]       f32

    const int B = in_sizes[2];
    const int T = in_sizes[0] / (B * LNUM);

    sort_kernel<<<1, MAXB>>>(lens, B);
    crf_fwd_kernel<<<B, NT>>>(logits, trans, lens, out, T);
}